// round 17
// baseline (speedup 1.0000x reference)
#include <cuda_runtime.h>
#include <cuda_fp16.h>
#include <cstdint>

// ---------------- problem constants ----------------
#define PN0 100000
#define PN1 50000
#define PN2 25000
#define PN3 12500
#define PB  8
#define PS  1024
#define NSEED (PB * PS)
#define C0 32
#define C1 64
#define C2 128
#define C3 256

// ---------------- scratch (device globals; no allocation allowed) ----------------
__device__ __align__(256) __half g_x0[PN0 * C0];
__device__ __align__(256) __half g_t0[PN0 * C0];
__device__ __align__(256) __half g_x1[PN1 * C1];
__device__ __align__(256) __half g_t1[PN1 * C1];
__device__ __align__(256) __half g_x2[PN2 * C2];
__device__ __align__(256) __half g_t2[PN2 * C2];
__device__ __align__(256) __half g_x3[PN3 * C3];
__device__ __align__(256) __half g_t3[PN3 * C3];

// fp16 conv weights transposed to [k][o][c]
__device__ __align__(256) __half g_wb0[27 * 32 * 32];
__device__ __align__(256) __half g_wd1[8 * 32 * 64];
__device__ __align__(256) __half g_wb1[27 * 64 * 64];
__device__ __align__(256) __half g_wd2[8 * 64 * 128];
__device__ __align__(256) __half g_wb2[27 * 128 * 128];
__device__ __align__(256) __half g_wd3[8 * 128 * 256];
__device__ __align__(256) __half g_wb3[27 * 256 * 256];

// fp16 decoder weights transposed to [o][c]
__device__ __align__(256) __half g_wu2[256 * 384];
__device__ __align__(256) __half g_wu1[128 * 320];
__device__ __align__(256) __half g_wu0[96 * 160];
__device__ __align__(256) __half g_wo[512 * 96];

// decoder seed-chain indices and intermediates
__device__ int g_chp[NSEED];
__device__ int g_ch1[NSEED];
__device__ int g_ch2[NSEED];
__device__ int g_ch3[NSEED];
__device__ __align__(256) __half g_ut2[NSEED * 256];
__device__ __align__(256) __half g_u2[NSEED * 256];
__device__ __align__(256) __half g_ut1[NSEED * 128];
__device__ __align__(256) __half g_u1[NSEED * 128];
__device__ __align__(256) __half g_ut0[NSEED * 96];
__device__ __align__(256) __half g_u0[NSEED * 96];

// ---------------- helpers ----------------
__device__ __forceinline__ void mma_f16(float d[4], const uint32_t a[4],
                                        uint32_t b0, uint32_t b1) {
    asm volatile(
        "mma.sync.aligned.m16n8k16.row.col.f32.f16.f16.f32 "
        "{%0,%1,%2,%3}, {%4,%5,%6,%7}, {%8,%9}, {%0,%1,%2,%3};\n"
        : "+f"(d[0]), "+f"(d[1]), "+f"(d[2]), "+f"(d[3])
        : "r"(a[0]), "r"(a[1]), "r"(a[2]), "r"(a[3]), "r"(b0), "r"(b1));
}
__device__ __forceinline__ void cp_async16(void* dst_smem, const void* src) {
    uint32_t d = (uint32_t)__cvta_generic_to_shared(dst_smem);
    asm volatile("cp.async.cg.shared.global [%0], [%1], 16;" :: "r"(d), "l"(src));
}
__device__ __forceinline__ void cp_commit() {
    asm volatile("cp.async.commit_group;");
}
template <int NN>
__device__ __forceinline__ void cp_wait() {
    asm volatile("cp.async.wait_group %0;" :: "n"(NN));
}

__host__ __device__ constexpr int cc_of(int cin) {
    return cin % 64 == 0 ? 64 : (cin == 96 ? 48 : cin);
}
__host__ __device__ constexpr int smem_g(int CIN, int NT, int ST) {
    return ST * (128 + NT) * (cc_of(CIN) + 8) * 2;
}

// ---------------- generalized fp16 gather-GEMM, ST-stage cp.async pipeline ----------------
// out[n,o] = epi( sum_k sum_c f[idx(n,k),c] * W[k][o][c] )
// IDX: 0 = nbr[n*KK+k], 1 = chain nbr[n], 2 = identity
// EPI: 0 = relu; 1 = relu then +resid (encoder residual);
//      2 = +resid then relu (concat split); 3 = linear fp16;
//      4 = linear fp32 transposed store to fout[b][o][si]
// Mainloop: one __syncthreads per stage; stages >= NSTAGE commit empty groups
// so cp_wait<ST-2> counting stays uniform.
template <int KK, int CIN, int COUT, int NT, int IDX, int EPI, int ST>
__global__ __launch_bounds__(256) void spconv_g(
    const __half* __restrict__ f, const int* __restrict__ nbr,
    const __half* __restrict__ Wt, int wpitch,
    const __half* __restrict__ resid,
    __half* __restrict__ out, float* __restrict__ fout, int N)
{
    constexpr int WM = (NT == 32) ? 8 : 4;
    constexpr int WN = 8 / WM;
    constexpr int WTM = 128 / WM;
    constexpr int WTN = NT / WN;
    constexpr int MF = WTM / 16;
    constexpr int NF = WTN / 8;
    constexpr int CC  = cc_of(CIN);
    constexpr int NCH = CIN / CC;
    constexpr int NSTAGE = KK * NCH;
    constexpr int AP = CC + 8;
    constexpr int BP = CC + 8;
    constexpr int A8 = CC / 8;
    constexpr int ABUF = 128 * AP;          // halves per A stage
    constexpr int BBUF = NT * BP;           // halves per B stage

    extern __shared__ __half smemh[];
    __half* sA0 = smemh;                    // [ST][128][AP]
    __half* sB0 = smemh + ST * ABUF;        // [ST][NT][BP]

    const int tid  = threadIdx.x;
    const int warp = tid >> 5;
    const int lane = tid & 31;
    const int gId  = lane >> 2;
    const int tig  = lane & 3;
    const int wm = warp % WM;
    const int wn = warp / WM;
    const int n0  = blockIdx.x * 128;
    const int nt0 = blockIdx.y * NT;

    auto stage = [&](int s) {
        if (s < NSTAGE) {
            const int buf = s % ST;
            const int k = s / NCH, ch = s % NCH;
            __half* dA = sA0 + buf * ABUF;
            __half* dB = sB0 + buf * BBUF;
#pragma unroll
            for (int i = tid; i < 128 * A8; i += 256) {
                int row = i / A8, c8 = i % A8;
                int n = n0 + row;
                int idx;
                if constexpr (IDX == 0)      idx = (n < N) ? __ldg(nbr + (size_t)n * KK + k) : 0;
                else if constexpr (IDX == 1) idx = (n < N) ? __ldg(nbr + n) : 0;
                else                         idx = (n < N) ? n : 0;
                cp_async16(dA + row * AP + c8 * 8,
                           f + (size_t)idx * CIN + ch * CC + c8 * 8);
            }
            const __half* WkT = Wt + ((size_t)k * COUT + nt0) * wpitch + ch * CC;
#pragma unroll
            for (int i = tid; i < NT * A8; i += 256) {
                int r = i / A8, c8 = i % A8;
                cp_async16(dB + r * BP + c8 * 8, WkT + (size_t)r * wpitch + c8 * 8);
            }
        }
        cp_commit();
    };

    float acc[MF][NF][4];
#pragma unroll
    for (int mf = 0; mf < MF; mf++)
#pragma unroll
        for (int nf = 0; nf < NF; nf++)
#pragma unroll
            for (int i = 0; i < 4; i++) acc[mf][nf][i] = 0.f;

    // prologue: issue stages 0..ST-2
#pragma unroll
    for (int p = 0; p < ST - 1; p++) stage(p);

    for (int s = 0; s < NSTAGE; s++) {
        cp_wait<ST - 2>();       // stage s arrived (committed = ST-1+s, pending <= ST-2)
        __syncthreads();         // all warps done with compute(s-1); buffer (s-1)%ST reusable
        stage(s + ST - 1);       // issue into buffer (s-1)%ST

        const __half* A = sA0 + (s % ST) * ABUF;
        const __half* B = sB0 + (s % ST) * BBUF;
#pragma unroll
        for (int k16 = 0; k16 < CC / 16; k16++) {
            const int k0 = k16 * 16;
            uint32_t a[MF][4];
#pragma unroll
            for (int mf = 0; mf < MF; mf++) {
                const __half* ap = A + (wm * WTM + mf * 16 + gId) * AP + k0 + 2 * tig;
                a[mf][0] = *(const uint32_t*)(ap);
                a[mf][1] = *(const uint32_t*)(ap + 8 * AP);
                a[mf][2] = *(const uint32_t*)(ap + 8);
                a[mf][3] = *(const uint32_t*)(ap + 8 * AP + 8);
            }
#pragma unroll
            for (int nf = 0; nf < NF; nf++) {
                const __half* bp = B + (wn * WTN + nf * 8 + gId) * BP + k0 + 2 * tig;
                uint32_t b0 = *(const uint32_t*)(bp);
                uint32_t b1 = *(const uint32_t*)(bp + 8);
#pragma unroll
                for (int mf = 0; mf < MF; mf++)
                    mma_f16(acc[mf][nf], a[mf], b0, b1);
            }
        }
    }

    // ---- epilogue ----
    auto emit = [&](int n, int o, float v0, float v1) {
        if (n >= N) return;
        if constexpr (EPI == 4) {
            int b = n >> 10, si = n & 1023;
            fout[((size_t)b * COUT + o)     * PS + si] = v0;
            fout[((size_t)b * COUT + o + 1) * PS + si] = v1;
        } else {
            float x = v0, y = v1;
            if constexpr (EPI == 2) {
                __half2 rr = *(const __half2*)(resid + (size_t)n * COUT + o);
                x += __half2float(__low2half(rr));
                y += __half2float(__high2half(rr));
            }
            if constexpr (EPI != 3) { x = fmaxf(x, 0.f); y = fmaxf(y, 0.f); }
            if constexpr (EPI == 1) {
                __half2 rr = *(const __half2*)(resid + (size_t)n * COUT + o);
                x += __half2float(__low2half(rr));
                y += __half2float(__high2half(rr));
            }
            *(__half2*)(out + (size_t)n * COUT + o) = __floats2half2_rn(x, y);
        }
    };

#pragma unroll
    for (int mf = 0; mf < MF; mf++) {
        const int r = wm * WTM + mf * 16 + gId;
#pragma unroll
        for (int nf = 0; nf < NF; nf++) {
            const int o = nt0 + wn * WTN + nf * 8 + 2 * tig;
            emit(n0 + r,     o, acc[mf][nf][0], acc[mf][nf][1]);
            emit(n0 + r + 8, o, acc[mf][nf][2], acc[mf][nf][3]);
        }
    }
}

// ---------------- fused prep: stem conv + weight conversions + seed chains ----------------
#define SB0_N (27 * 32 * 32)
#define SD1_N (8 * 32 * 64)
#define SB1_N (27 * 64 * 64)
#define SD2_N (8 * 64 * 128)
#define SB2_N (27 * 128 * 128)
#define SD3_N (8 * 128 * 256)
#define SB3_N (27 * 256 * 256)
#define SU2_N (384 * 256)
#define SU1_N (320 * 128)
#define SU0_N (160 * 96)
#define SWO_N (96 * 512)
#define STEM_BLKS ((PN0 + 31) / 32)
#define CHAIN_BLKS (NSEED / 256)
#define NB(x) (((x) + 255) / 256)
#define PREP_BLKS (STEM_BLKS + CHAIN_BLKS + NB(SB0_N) + NB(SD1_N) + NB(SB1_N) + \
                   NB(SD2_N) + NB(SB2_N) + NB(SD3_N) + NB(SB3_N) + \
                   NB(SU2_N) + NB(SU1_N) + NB(SU0_N) + NB(SWO_N))

__device__ __forceinline__ void cvt_conv(const float* s, __half* d,
                                         int Cin, int Cout, int i, int total) {
    if (i < total) {
        int kco = Cin * Cout;
        int k = i / kco, r = i % kco;
        int c = r / Cout, o = r % Cout;
        d[((size_t)k * Cout + o) * Cin + c] = __float2half_rn(s[i]);
    }
}
__device__ __forceinline__ void cvt_lin(const float* s, __half* d,
                                        int Cin, int Cout, int i, int total) {
    if (i < total) {
        int c = i / Cout, o = i % Cout;
        d[(size_t)o * Cin + c] = __float2half_rn(s[i]);
    }
}

__global__ __launch_bounds__(256) void prep_kernel(
    const float* __restrict__ feats, const int* __restrict__ nbr0,
    const float* __restrict__ W_stem, __half* __restrict__ x0out,
    const float* Wb0, const float* Wd1, const float* Wb1, const float* Wd2,
    const float* Wb2, const float* Wd3, const float* Wb3,
    const float* Wu2, const float* Wu1, const float* Wu0, const float* Wout,
    const int* __restrict__ up0, const int* __restrict__ up1,
    const int* __restrict__ up2, const int* __restrict__ seed)
{
    __shared__ __align__(16) float As[32][3];
    __shared__ int s_idx[32 * 27];

    const int tid = threadIdx.x;
    int bid = blockIdx.x;

    if (bid < STEM_BLKS) {
        const int n0 = bid * 32;
        const int o = tid % 32;
        const int mg = tid / 32;
        for (int i = tid; i < 32 * 27; i += 256) {
            int n = n0 + i / 27;
            s_idx[i] = (n < PN0) ? nbr0[(size_t)n0 * 27 + i] : 0;
        }
        float acc[4] = {0.f, 0.f, 0.f, 0.f};
        for (int k = 0; k < 27; k++) {
            __syncthreads();
            for (int i = tid; i < 32 * 3; i += 256) {
                int m = i / 3, c = i % 3;
                As[m][c] = __ldg(feats + (size_t)s_idx[m * 27 + k] * 3 + c);
            }
            __syncthreads();
            const float* Wk = W_stem + (size_t)k * 3 * 32;
            for (int c = 0; c < 3; c++) {
                float w = __ldg(Wk + (size_t)c * 32 + o);
#pragma unroll
                for (int mi = 0; mi < 4; mi++)
                    acc[mi] += As[mg * 4 + mi][c] * w;
            }
        }
#pragma unroll
        for (int mi = 0; mi < 4; mi++) {
            int n = n0 + mg * 4 + mi;
            if (n < PN0)
                x0out[(size_t)n * 32 + o] = __float2half_rn(fmaxf(acc[mi], 0.f));
        }
        return;
    }
    bid -= STEM_BLKS;

    if (bid < CHAIN_BLKS) {
        int i = bid * 256 + tid;
        if (i < NSEED) {
            int p = seed[i];
            int j1 = up0[p];
            int j2 = up1[j1];
            int j3 = up2[j2];
            g_chp[i] = p; g_ch1[i] = j1; g_ch2[i] = j2; g_ch3[i] = j3;
        }
        return;
    }
    bid -= CHAIN_BLKS;

    if (bid < NB(SB0_N)) { cvt_conv(Wb0, g_wb0, 32, 32,  bid * 256 + tid, SB0_N); return; }
    bid -= NB(SB0_N);
    if (bid < NB(SD1_N)) { cvt_conv(Wd1, g_wd1, 32, 64,  bid * 256 + tid, SD1_N); return; }
    bid -= NB(SD1_N);
    if (bid < NB(SB1_N)) { cvt_conv(Wb1, g_wb1, 64, 64,  bid * 256 + tid, SB1_N); return; }
    bid -= NB(SB1_N);
    if (bid < NB(SD2_N)) { cvt_conv(Wd2, g_wd2, 64, 128, bid * 256 + tid, SD2_N); return; }
    bid -= NB(SD2_N);
    if (bid < NB(SB2_N)) { cvt_conv(Wb2, g_wb2, 128, 128, bid * 256 + tid, SB2_N); return; }
    bid -= NB(SB2_N);
    if (bid < NB(SD3_N)) { cvt_conv(Wd3, g_wd3, 128, 256, bid * 256 + tid, SD3_N); return; }
    bid -= NB(SD3_N);
    if (bid < NB(SB3_N)) { cvt_conv(Wb3, g_wb3, 256, 256, bid * 256 + tid, SB3_N); return; }
    bid -= NB(SB3_N);
    if (bid < NB(SU2_N)) { cvt_lin(Wu2, g_wu2, 384, 256, bid * 256 + tid, SU2_N); return; }
    bid -= NB(SU2_N);
    if (bid < NB(SU1_N)) { cvt_lin(Wu1, g_wu1, 320, 128, bid * 256 + tid, SU1_N); return; }
    bid -= NB(SU1_N);
    if (bid < NB(SU0_N)) { cvt_lin(Wu0, g_wu0, 160, 96, bid * 256 + tid, SU0_N); return; }
    bid -= NB(SU0_N);
    if (bid < NB(SWO_N)) { cvt_lin(Wout, g_wo, 96, 512, bid * 256 + tid, SWO_N); return; }
}

// ---------------- launch ----------------
extern "C" void kernel_launch(void* const* d_in, const int* in_sizes, int n_in,
                              void* d_out, int out_size)
{
    (void)in_sizes; (void)n_in; (void)out_size;
    const float* feats   = (const float*)d_in[0];
    const int*   nbr0    = (const int*)d_in[1];
    const int*   nbr1    = (const int*)d_in[2];
    const int*   nbr2    = (const int*)d_in[3];
    const int*   nbr3    = (const int*)d_in[4];
    const int*   down1   = (const int*)d_in[5];
    const int*   down2   = (const int*)d_in[6];
    const int*   down3   = (const int*)d_in[7];
    const int*   up2     = (const int*)d_in[8];
    const int*   up1     = (const int*)d_in[9];
    const int*   up0     = (const int*)d_in[10];
    const int*   seedidx = (const int*)d_in[11];
    const float* W_stem  = (const float*)d_in[12];
    const float* W_b0    = (const float*)d_in[13];
    const float* W_d1    = (const float*)d_in[14];
    const float* W_b1    = (const float*)d_in[15];
    const float* W_d2    = (const float*)d_in[16];
    const float* W_b2    = (const float*)d_in[17];
    const float* W_d3    = (const float*)d_in[18];
    const float* W_b3    = (const float*)d_in[19];
    const float* W_u2    = (const float*)d_in[20];
    const float* W_u1    = (const float*)d_in[21];
    const float* W_u0    = (const float*)d_in[22];
    const float* W_out   = (const float*)d_in[23];

    __half *px0, *pt0, *px1, *pt1, *px2, *pt2, *px3, *pt3;
    cudaGetSymbolAddress((void**)&px0, g_x0);
    cudaGetSymbolAddress((void**)&pt0, g_t0);
    cudaGetSymbolAddress((void**)&px1, g_x1);
    cudaGetSymbolAddress((void**)&pt1, g_t1);
    cudaGetSymbolAddress((void**)&px2, g_x2);
    cudaGetSymbolAddress((void**)&pt2, g_t2);
    cudaGetSymbolAddress((void**)&px3, g_x3);
    cudaGetSymbolAddress((void**)&pt3, g_t3);

    __half *wb0, *wd1, *wb1, *wd2, *wb2, *wd3, *wb3, *wu2, *wu1, *wu0, *wo;
    cudaGetSymbolAddress((void**)&wb0, g_wb0);
    cudaGetSymbolAddress((void**)&wd1, g_wd1);
    cudaGetSymbolAddress((void**)&wb1, g_wb1);
    cudaGetSymbolAddress((void**)&wd2, g_wd2);
    cudaGetSymbolAddress((void**)&wb2, g_wb2);
    cudaGetSymbolAddress((void**)&wd3, g_wd3);
    cudaGetSymbolAddress((void**)&wb3, g_wb3);
    cudaGetSymbolAddress((void**)&wu2, g_wu2);
    cudaGetSymbolAddress((void**)&wu1, g_wu1);
    cudaGetSymbolAddress((void**)&wu0, g_wu0);
    cudaGetSymbolAddress((void**)&wo,  g_wo);

    int *chp, *ch1, *ch2, *ch3;
    cudaGetSymbolAddress((void**)&chp, g_chp);
    cudaGetSymbolAddress((void**)&ch1, g_ch1);
    cudaGetSymbolAddress((void**)&ch2, g_ch2);
    cudaGetSymbolAddress((void**)&ch3, g_ch3);

    __half *ut2, *u2b, *ut1, *u1b, *ut0, *u0b;
    cudaGetSymbolAddress((void**)&ut2, g_ut2);
    cudaGetSymbolAddress((void**)&u2b, g_u2);
    cudaGetSymbolAddress((void**)&ut1, g_ut1);
    cudaGetSymbolAddress((void**)&u1b, g_u1);
    cudaGetSymbolAddress((void**)&ut0, g_ut0);
    cudaGetSymbolAddress((void**)&u0b, g_u0);

    // smem attributes (host-side, idempotent)
    auto setsm = [](const void* fn, int b) {
        cudaFuncSetAttribute(fn, cudaFuncAttributeMaxDynamicSharedMemorySize, b);
    };
    setsm((const void*)spconv_g<27, 32, 32, 32, 0, 1, 4>,    smem_g(32, 32, 4));
    setsm((const void*)spconv_g<8, 32, 64, 64, 0, 0, 4>,     smem_g(32, 64, 4));
    setsm((const void*)spconv_g<27, 64, 64, 64, 0, 1, 3>,    smem_g(64, 64, 3));
    setsm((const void*)spconv_g<8, 64, 128, 128, 0, 0, 3>,   smem_g(64, 128, 3));
    setsm((const void*)spconv_g<27, 128, 128, 128, 0, 1, 3>, smem_g(128, 128, 3));
    setsm((const void*)spconv_g<8, 128, 256, 128, 0, 0, 3>,  smem_g(128, 128, 3));
    setsm((const void*)spconv_g<27, 256, 256, 128, 0, 1, 3>, smem_g(256, 128, 3));
    setsm((const void*)spconv_g<1, 256, 256, 128, 1, 3, 3>,  smem_g(256, 128, 3));
    setsm((const void*)spconv_g<1, 128, 256, 128, 1, 2, 3>,  smem_g(128, 128, 3));
    setsm((const void*)spconv_g<1, 256, 128, 128, 2, 3, 3>,  smem_g(256, 128, 3));
    setsm((const void*)spconv_g<1, 64, 128, 128, 1, 2, 3>,   smem_g(64, 128, 3));
    setsm((const void*)spconv_g<1, 128, 96, 32, 2, 3, 3>,    smem_g(128, 32, 3));
    setsm((const void*)spconv_g<1, 32, 96, 32, 1, 2, 3>,     smem_g(32, 32, 3));
    setsm((const void*)spconv_g<1, 96, 512, 128, 2, 4, 3>,   smem_g(96, 128, 3));

    const int gm0 = (PN0 + 127) / 128;
    const int gm1 = (PN1 + 127) / 128;
    const int gm2 = (PN2 + 127) / 128;
    const int gm3 = (PN3 + 127) / 128;
    const int gms = NSEED / 128;  // 64

    // 1) fused prep: stem + all weight cvt + seed chains
    prep_kernel<<<PREP_BLKS, 256>>>(
        feats, nbr0, W_stem, px0,
        W_b0, W_d1, W_b1, W_d2, W_b2, W_d3, W_b3,
        W_u2, W_u1, W_u0, W_out,
        up0, up1, up2, seedidx);

    // 2) encoder (fp16 tensor-core gather-GEMMs)
    spconv_g<27, 32, 32, 32, 0, 1, 4><<<dim3(gm0, 1), 256, smem_g(32, 32, 4)>>>(
        px0, nbr0, wb0, 32, px0, pt0, nullptr, PN0);
    spconv_g<8, 32, 64, 64, 0, 0, 4><<<dim3(gm1, 1), 256, smem_g(32, 64, 4)>>>(
        pt0, down1, wd1, 32, nullptr, px1, nullptr, PN1);
    spconv_g<27, 64, 64, 64, 0, 1, 3><<<dim3(gm1, 1), 256, smem_g(64, 64, 3)>>>(
        px1, nbr1, wb1, 64, px1, pt1, nullptr, PN1);
    spconv_g<8, 64, 128, 128, 0, 0, 3><<<dim3(gm2, 1), 256, smem_g(64, 128, 3)>>>(
        pt1, down2, wd2, 64, nullptr, px2, nullptr, PN2);
    spconv_g<27, 128, 128, 128, 0, 1, 3><<<dim3(gm2, 1), 256, smem_g(128, 128, 3)>>>(
        px2, nbr2, wb2, 128, px2, pt2, nullptr, PN2);
    spconv_g<8, 128, 256, 128, 0, 0, 3><<<dim3(gm3, 2), 256, smem_g(128, 128, 3)>>>(
        pt2, down3, wd3, 128, nullptr, px3, nullptr, PN3);
    spconv_g<27, 256, 256, 128, 0, 1, 3><<<dim3(gm3, 2), 256, smem_g(256, 128, 3)>>>(
        px3, nbr3, wb3, 256, px3, pt3, nullptr, PN3);

    // 3) decoder as gather-GEMM passes over seed chains
    spconv_g<1, 256, 256, 128, 1, 3, 3><<<dim3(gms, 2), 256, smem_g(256, 128, 3)>>>(
        pt3, ch3, wu2, 384, nullptr, ut2, nullptr, NSEED);
    spconv_g<1, 128, 256, 128, 1, 2, 3><<<dim3(gms, 2), 256, smem_g(128, 128, 3)>>>(
        pt2, ch2, wu2 + 256, 384, ut2, u2b, nullptr, NSEED);
    spconv_g<1, 256, 128, 128, 2, 3, 3><<<dim3(gms, 1), 256, smem_g(256, 128, 3)>>>(
        u2b, nullptr, wu1, 320, nullptr, ut1, nullptr, NSEED);
    spconv_g<1, 64, 128, 128, 1, 2, 3><<<dim3(gms, 1), 256, smem_g(64, 128, 3)>>>(
        pt1, ch1, wu1 + 256, 320, ut1, u1b, nullptr, NSEED);
    spconv_g<1, 128, 96, 32, 2, 3, 3><<<dim3(gms, 3), 256, smem_g(128, 32, 3)>>>(
        u1b, nullptr, wu0, 160, nullptr, ut0, nullptr, NSEED);
    spconv_g<1, 32, 96, 32, 1, 2, 3><<<dim3(gms, 3), 256, smem_g(32, 32, 3)>>>(
        pt0, chp, wu0 + 128, 160, ut0, u0b, nullptr, NSEED);
    spconv_g<1, 96, 512, 128, 2, 4, 3><<<dim3(gms, 4), 256, smem_g(96, 128, 3)>>>(
        u0b, nullptr, wo, 96, nullptr, nullptr, (float*)d_out, NSEED);
}